// round 1
// baseline (speedup 1.0000x reference)
#include <cuda_runtime.h>

#define NN 50000
#define EE 800000
#define D  128

// ---------------- persistent device scratch (no allocations allowed) -------
__device__ int   g_degE[NN];
__device__ float g_dinv[NN];
__device__ int   g_rowPtr[NN + 1];
__device__ int   g_cursor[NN];
__device__ int   g_src[EE];
__device__ float g_h[(size_t)NN * D];   // GEMM output
__device__ float g_a[(size_t)NN * D];   // post-aggregation features
__device__ float g_gsum[D];             // pooled sum

// ---------------- setup kernels --------------------------------------------
__global__ void k_init() {
    int i = blockIdx.x * blockDim.x + threadIdx.x;
    if (i < NN) { g_degE[i] = 0; g_cursor[i] = 0; }
    if (i < D) g_gsum[i] = 0.f;
}

__global__ void k_count(const int* __restrict__ col) {
    int e = blockIdx.x * blockDim.x + threadIdx.x;
    if (e < EE) atomicAdd(&g_degE[col[e]], 1);
}

// single-block exclusive scan over g_degE -> g_rowPtr; also dinv = rsqrt(deg+1)
__global__ void k_scan() {
    __shared__ int s[1024];
    int t = threadIdx.x;
    int offset = 0;
    for (int base = 0; base < NN; base += 1024) {
        int i = base + t;
        int v = (i < NN) ? g_degE[i] : 0;
        if (i < NN) g_dinv[i] = rsqrtf((float)(v + 1));  // +1 self loop
        s[t] = v;
        __syncthreads();
        for (int d = 1; d < 1024; d <<= 1) {
            int add = (t >= d) ? s[t - d] : 0;
            __syncthreads();
            s[t] += add;
            __syncthreads();
        }
        if (i < NN) g_rowPtr[i] = offset + s[t] - v;   // exclusive
        offset += s[1023];
        __syncthreads();
    }
    if (t == 0) g_rowPtr[NN] = offset;
}

__global__ void k_scatter(const int* __restrict__ row, const int* __restrict__ col) {
    int e = blockIdx.x * blockDim.x + threadIdx.x;
    if (e < EE) {
        int c = col[e];
        int pos = g_rowPtr[c] + atomicAdd(&g_cursor[c], 1);
        g_src[pos] = row[e];
    }
}

// ---------------- dense GEMM: Y[N,128] = X[N,128] @ W[128,128] -------------
// block = 256 threads computes 64 rows x 128 cols. W staged in smem in two
// 64-row halves (32KB static). X read via broadcast float4 LDG (L1-resident).
__global__ void __launch_bounds__(256) k_gemm(const float* __restrict__ X,
                                              const float* __restrict__ W,
                                              float* __restrict__ Y) {
    __shared__ float sW[64 * 128];
    const int tx = threadIdx.x & 31;   // col group: 4 consecutive cols
    const int ty = threadIdx.x >> 5;   // row group: 8 rows
    const int row0 = blockIdx.x * 64 + ty * 8;

    float4 acc[8];
#pragma unroll
    for (int i = 0; i < 8; i++) acc[i] = make_float4(0.f, 0.f, 0.f, 0.f);

    for (int kp = 0; kp < 2; kp++) {
        // stage W[kp*64 .. kp*64+63][:]  (8192 floats = 2048 float4)
        const float4* Wv = (const float4*)(W + kp * 64 * 128);
        float4* sWv = (float4*)sW;
#pragma unroll
        for (int j = 0; j < 8; j++)
            sWv[threadIdx.x + j * 256] = Wv[threadIdx.x + j * 256];
        __syncthreads();

#pragma unroll 4
        for (int k4 = 0; k4 < 16; k4++) {
            const int k = kp * 64 + k4 * 4;
            float4 xv[8];
#pragma unroll
            for (int i = 0; i < 8; i++) {
                int r = row0 + i;
                xv[i] = (r < NN) ? *(const float4*)(X + (size_t)r * 128 + k)
                                 : make_float4(0.f, 0.f, 0.f, 0.f);
            }
#pragma unroll
            for (int j = 0; j < 4; j++) {
                float4 w = *(const float4*)(sW + (k4 * 4 + j) * 128 + tx * 4);
#pragma unroll
                for (int i = 0; i < 8; i++) {
                    float xs = (j == 0) ? xv[i].x : (j == 1) ? xv[i].y
                             : (j == 2) ? xv[i].z : xv[i].w;
                    acc[i].x += xs * w.x;
                    acc[i].y += xs * w.y;
                    acc[i].z += xs * w.z;
                    acc[i].w += xs * w.w;
                }
            }
        }
        __syncthreads();
    }
#pragma unroll
    for (int i = 0; i < 8; i++) {
        int r = row0 + i;
        if (r < NN) *(float4*)(Y + (size_t)r * 128 + tx * 4) = acc[i];
    }
}

// ---------------- sparse aggregation (warp per node) -----------------------
// agg[c] = dinv[c] * sum_{r in N(c)} dinv[r]*H[r]  +  dinv[c]^2 * H[c]
// out    = relu(agg + bias);  optionally accumulate pooled sum.
template <bool POOL>
__global__ void __launch_bounds__(256) k_agg(const float* __restrict__ H,
                                             const float* __restrict__ bias,
                                             float* __restrict__ O) {
    __shared__ float sPool[128];
    const int lane = threadIdx.x & 31;
    const int w    = threadIdx.x >> 5;
    if (POOL) {
        if (threadIdx.x < 128) sPool[threadIdx.x] = 0.f;
        __syncthreads();
    }
    const int node = blockIdx.x * 8 + w;
    if (node < NN) {
        const int s = g_rowPtr[node];
        const int e = g_rowPtr[node + 1];
        const float4* Hv = (const float4*)H;
        float4 acc = make_float4(0.f, 0.f, 0.f, 0.f);
        for (int i = s; i < e; i++) {
            int r = g_src[i];
            float dr = g_dinv[r];
            float4 v = Hv[(size_t)r * 32 + lane];
            acc.x += dr * v.x;
            acc.y += dr * v.y;
            acc.z += dr * v.z;
            acc.w += dr * v.w;
        }
        const float dc = g_dinv[node];
        const float dc2 = dc * dc;
        float4 sv = Hv[(size_t)node * 32 + lane];
        float4 b  = ((const float4*)bias)[lane];
        float4 res;
        res.x = fmaxf(dc * acc.x + dc2 * sv.x + b.x, 0.f);
        res.y = fmaxf(dc * acc.y + dc2 * sv.y + b.y, 0.f);
        res.z = fmaxf(dc * acc.z + dc2 * sv.z + b.z, 0.f);
        res.w = fmaxf(dc * acc.w + dc2 * sv.w + b.w, 0.f);
        *(float4*)(O + (size_t)node * 128 + lane * 4) = res;
        if (POOL) {
            atomicAdd(&sPool[lane * 4 + 0], res.x);
            atomicAdd(&sPool[lane * 4 + 1], res.y);
            atomicAdd(&sPool[lane * 4 + 2], res.z);
            atomicAdd(&sPool[lane * 4 + 3], res.w);
        }
    }
    if (POOL) {
        __syncthreads();
        if (threadIdx.x < 128) atomicAdd(&g_gsum[threadIdx.x], sPool[threadIdx.x]);
    }
}

// ---------------- classifier head ------------------------------------------
__global__ void k_cls(const float* __restrict__ Wc, const float* __restrict__ bc,
                      float* __restrict__ out) {
    int o = threadIdx.x;
    if (o < 40) {
        float acc = 0.f;
        for (int k = 0; k < 128; k++) acc += g_gsum[k] * Wc[k * 40 + o];
        out[o] = acc * (1.0f / (float)NN) + bc[o];
    }
}

// ---------------- launch ----------------------------------------------------
extern "C" void kernel_launch(void* const* d_in, const int* in_sizes, int n_in,
                              void* d_out, int out_size) {
    const float* x  = (const float*)d_in[0];
    const int*   ei = (const int*)d_in[1];
    const float* W1 = (const float*)d_in[2];
    const float* b1 = (const float*)d_in[3];
    const float* W2 = (const float*)d_in[4];
    const float* b2 = (const float*)d_in[5];
    const float* Wc = (const float*)d_in[6];
    const float* bc = (const float*)d_in[7];
    const int* row = ei;        // edge_index[0]
    const int* col = ei + EE;   // edge_index[1]

    float *h_ptr, *a_ptr;
    cudaGetSymbolAddress((void**)&h_ptr, g_h);
    cudaGetSymbolAddress((void**)&a_ptr, g_a);

    k_init<<<(NN + 255) / 256, 256>>>();
    k_count<<<(EE + 255) / 256, 256>>>(col);
    k_scan<<<1, 1024>>>();
    k_scatter<<<(EE + 255) / 256, 256>>>(row, col);

    k_gemm<<<(NN + 63) / 64, 256>>>(x, W1, h_ptr);
    k_agg<false><<<(NN + 7) / 8, 256>>>(h_ptr, b1, a_ptr);
    k_gemm<<<(NN + 63) / 64, 256>>>(a_ptr, W2, h_ptr);
    k_agg<true><<<(NN + 7) / 8, 256>>>(h_ptr, b2, a_ptr);
    k_cls<<<1, 64>>>(Wc, bc, (float*)d_out);
}